// round 14
// baseline (speedup 1.0000x reference)
#include <cuda_runtime.h>
#include <cuda_fp16.h>
#include <cstdint>
#include <cstring>

// Problem constants (fixed by the reference)
#define NN      100000
#define D_IN    256
#define D_OUT   128
#define NNZ_X   3200000
#define NNZ_A   3200000
#define INV_KEEP 1.1111112f   // float32(1/0.9), matching JAX

#define CAP     96            // bucket capacity per row; P(Poisson(32) > 96) ~ 1e-20

#define SCAT_BLKS   (NNZ_X / 4 / 256)      // 3125 blocks, 4 nnz/thread
#define SPMM1_BLKS  (NN / 16)              // 6250 blocks, 16 rows per block (8 warps x 2)

// ---------------------------------------------------------------------------
// Static scratch (no allocations allowed). +8 entry tail pad: the pipelined
// gather loops prefetch up to 2 entries past a row's CAP region.
// ---------------------------------------------------------------------------
__device__ __half g_h[(size_t)NN * D_OUT];          // 25.6 MB  H = X@W (fp16)
__device__ __half g_w16[D_IN * D_OUT];              // 64 KB    W in fp16
__device__ int    g_fill[2 * NN];                   // fillX | fillA
__device__ int2   g_bktX[(size_t)NN * CAP + 8];     // 76.8 MB (col, val-bits)
__device__ int2   g_bktA[(size_t)NN * CAP + 8];     // 76.8 MB

// bit-cast helpers
__device__ __forceinline__ uint32_t h2_to_u32(half2 h) {
    uint32_t u; memcpy(&u, &h, 4); return u;
}
__device__ __forceinline__ half2 u32_to_h2(uint32_t u) {
    half2 h; memcpy(&h, &u, 4); return h;
}

// ---------------------------------------------------------------------------
// Packed f32x2 helpers (Blackwell FFMA2 via PTX fma.rn.f32x2).
// Element-wise round-to-nearest — bit-identical to the scalar FFMA sequence.
// ---------------------------------------------------------------------------
__device__ __forceinline__ uint64_t pack_f32x2(float lo, float hi) {
    uint64_t p;
    asm("mov.b64 %0, {%1, %2};" : "=l"(p) : "f"(lo), "f"(hi));
    return p;
}
__device__ __forceinline__ void unpack_f32x2(uint64_t p, float& lo, float& hi) {
    asm("mov.b64 {%0, %1}, %2;" : "=f"(lo), "=f"(hi) : "l"(p));
}
__device__ __forceinline__ void ffma2(uint64_t& acc, uint64_t a, uint64_t b) {
    asm("fma.rn.f32x2 %0, %1, %2, %0;" : "+l"(acc) : "l"(a), "l"(b));
}

// fma of 8 halves (uint4) scaled by packed (v,v) into 4 packed accumulators
__device__ __forceinline__ void fma_h16_p(uint64_t& c0, uint64_t& c1,
                                          uint64_t& c2, uint64_t& c3,
                                          uint64_t vv, uint4 q) {
    float2 f0 = __half22float2(u32_to_h2(q.x));
    float2 f1 = __half22float2(u32_to_h2(q.y));
    float2 f2 = __half22float2(u32_to_h2(q.z));
    float2 f3 = __half22float2(u32_to_h2(q.w));
    ffma2(c0, pack_f32x2(f0.x, f0.y), vv);
    ffma2(c1, pack_f32x2(f1.x, f1.y), vv);
    ffma2(c2, pack_f32x2(f2.x, f2.y), vv);
    ffma2(c3, pack_f32x2(f3.x, f3.y), vv);
}

__device__ __forceinline__ uint64_t bcast_f32x2(float v) {
    uint64_t p;
    asm("mov.b64 %0, {%1, %1};" : "=l"(p) : "f"(v));
    return p;
}

// ---------------------------------------------------------------------------
// threefry2x32, key = seed(42), partitionable mode: in = (0, i), out = o0^o1
// ---------------------------------------------------------------------------
__device__ __forceinline__ uint32_t rotl32(uint32_t v, int d) {
    return (v << d) | (v >> (32 - d));
}

__device__ __forceinline__ uint32_t threefry_bits_k42(uint32_t idx) {
    const uint32_t ks1 = 42u;
    const uint32_t ks2 = 42u ^ 0x1BD11BDAu;
    uint32_t x0 = 0u;
    uint32_t x1 = idx + ks1;
#define TF_ROUND(r) { x0 += x1; x1 = rotl32(x1, r); x1 ^= x0; }
    TF_ROUND(13) TF_ROUND(15) TF_ROUND(26) TF_ROUND(6)
    x0 += ks1; x1 += ks2 + 1u;
    TF_ROUND(17) TF_ROUND(29) TF_ROUND(16) TF_ROUND(24)
    x0 += ks2; x1 += 0u + 2u;
    TF_ROUND(13) TF_ROUND(15) TF_ROUND(26) TF_ROUND(6)
    x0 += 0u; x1 += ks1 + 3u;
    TF_ROUND(17) TF_ROUND(29) TF_ROUND(16) TF_ROUND(24)
    x0 += ks1; x1 += ks2 + 4u;
    TF_ROUND(13) TF_ROUND(15) TF_ROUND(26) TF_ROUND(6)
    x0 += ks2; x1 += 0u + 5u;
#undef TF_ROUND
    return x0 ^ x1;
}

__device__ __forceinline__ float bits_to_uniform(uint32_t bits) {
    return __uint_as_float((bits >> 9) | 0x3f800000u) - 1.0f;
}

// ---------------------------------------------------------------------------
// Prep: zero fill counters (2*NN ints = 50000 int4) + convert W to fp16
// ---------------------------------------------------------------------------
#define FILL_I4  (2 * NN / 4)                 // 50000
#define WCONV    (D_IN * D_OUT / 2)           // 16384 half2 outputs

__global__ void k_prep(const float* __restrict__ W) {
    int i = blockIdx.x * blockDim.x + threadIdx.x;
    if (i < FILL_I4) {
        ((int4*)g_fill)[i] = make_int4(0, 0, 0, 0);
    } else if (i < FILL_I4 + WCONV) {
        int j = i - FILL_I4;                   // half2 index
        float2 f = ((const float2*)W)[j];
        ((half2*)g_w16)[j] = __floats2half2_rn(f.x, f.y);
    }
}

// ---------------------------------------------------------------------------
// Scatter X into row buckets, 4 nnz per thread, dropout fused
// ---------------------------------------------------------------------------
__global__ void k_scatter_x(const int* __restrict__ x_rows,
                            const int* __restrict__ x_cols,
                            const float* __restrict__ x_vals) {
    int i = (blockIdx.x * blockDim.x + threadIdx.x) * 4;
    if (i >= NNZ_X) return;
    int4   r4 = __ldg((const int4*)(x_rows + i));
    int4   c4 = __ldg((const int4*)(x_cols + i));
    float4 v4 = __ldg((const float4*)(x_vals + i));
    #pragma unroll
    for (int k = 0; k < 4; k++) {
        int   r = (&r4.x)[k];
        int   c = (&c4.x)[k];
        float v = (&v4.x)[k];
        uint32_t bits = threefry_bits_k42((uint32_t)(i + k));
        float u = bits_to_uniform(bits);
        if (0.9f + u < 1.0f) continue;     // dropped, skip entirely
        int slot = atomicAdd(g_fill + r, 1);
        if (slot < CAP)
            g_bktX[(size_t)r * CAP + slot] =
                make_int2(c, __float_as_int(v * INV_KEEP));
    }
}

// ---------------------------------------------------------------------------
// Fused launch with INTERLEAVED roles: of every 3 consecutive blocks, 2 run
// SpMM1 and 1 runs scatterA, so both kinds coexist in every scheduling wave
// (a contiguous range split serializes across waves — measured in R12).
// ---------------------------------------------------------------------------
__global__ void k_spmm1_scatter_a(const int* __restrict__ a_rows,
                                  const int* __restrict__ a_cols,
                                  const float* __restrict__ a_vals,
                                  __half* __restrict__ H) {
    int b = blockIdx.x;
    int grp = b / 3;
    int rem = b - grp * 3;
    if (rem != 2) {
        // SpMM1 block index: 2 per group
        int sb = grp * 2 + rem;                  // < SPMM1_BLKS
        int lane = threadIdx.x & 31;
        int sub = lane >> 4;              // 0/1: which row of the pair
        int sl  = lane & 15;              // lane-within-row, owns cols [sl*8, sl*8+8)
        int row = sb * 16 + (threadIdx.x >> 5) * 2 + sub;
        int n = __ldg(g_fill + row);
        if (n > CAP) n = CAP;
        const int2*  bkt = g_bktX + (size_t)row * CAP;
        const int4*  b4  = (const int4*)bkt;                 // pair of entries
        const uint4* W4  = (const uint4*)g_w16;              // 8 halves per uint4
        uint64_t c0 = 0, c1 = 0, c2 = 0, c3 = 0;             // packed f32x2 accs
        int j = 0;
        if (j + 3 < n) {
            int4 pA = __ldg(b4);
            int4 pB = __ldg(b4 + 1);
            for (; j + 3 < n; j += 4) {
                int kn = (j >> 1) + 2;
                int4 pA2 = __ldg(b4 + kn);   // may overread into pad: unused then
                int4 pB2 = __ldg(b4 + kn + 1);
                uint4 q0 = __ldg(W4 + (size_t)pA.x * 16 + sl);
                uint4 q1 = __ldg(W4 + (size_t)pA.z * 16 + sl);
                uint4 q2 = __ldg(W4 + (size_t)pB.x * 16 + sl);
                uint4 q3 = __ldg(W4 + (size_t)pB.z * 16 + sl);
                fma_h16_p(c0, c1, c2, c3, bcast_f32x2(__int_as_float(pA.y)), q0);
                fma_h16_p(c0, c1, c2, c3, bcast_f32x2(__int_as_float(pA.w)), q1);
                fma_h16_p(c0, c1, c2, c3, bcast_f32x2(__int_as_float(pB.y)), q2);
                fma_h16_p(c0, c1, c2, c3, bcast_f32x2(__int_as_float(pB.w)), q3);
                pA = pA2; pB = pB2;
            }
        }
        for (; j < n; j++) {
            int2 cv = __ldg(bkt + j);
            uint4 q = __ldg(W4 + (size_t)cv.x * 16 + sl);
            fma_h16_p(c0, c1, c2, c3, bcast_f32x2(__int_as_float(cv.y)), q);
        }
        float lo, hi;
        uint4 packed;
        unpack_f32x2(c0, lo, hi); packed.x = h2_to_u32(__floats2half2_rn(lo, hi));
        unpack_f32x2(c1, lo, hi); packed.y = h2_to_u32(__floats2half2_rn(lo, hi));
        unpack_f32x2(c2, lo, hi); packed.z = h2_to_u32(__floats2half2_rn(lo, hi));
        unpack_f32x2(c3, lo, hi); packed.w = h2_to_u32(__floats2half2_rn(lo, hi));
        ((uint4*)H)[(size_t)row * 16 + sl] = packed;
    } else {
        // scatterA block index: 1 per group
        int i = (grp * 256 + threadIdx.x) * 4;
        if (i >= NNZ_A) return;
        int4   r4 = __ldg((const int4*)(a_rows + i));
        int4   c4 = __ldg((const int4*)(a_cols + i));
        float4 v4 = __ldg((const float4*)(a_vals + i));
        #pragma unroll
        for (int k = 0; k < 4; k++) {
            int   r = (&r4.x)[k];
            int   c = (&c4.x)[k];
            float v = (&v4.x)[k];
            int slot = atomicAdd(g_fill + NN + r, 1);
            if (slot < CAP)
                g_bktA[(size_t)r * CAP + slot] = make_int2(c, __float_as_int(v));
        }
    }
}

// ---------------------------------------------------------------------------
// SpMM2 + ReLU: out(fp32) = relu(A @ H).  2 rows/warp, pipelined unroll 4,
// packed f32x2 accumulation.
// ---------------------------------------------------------------------------
__global__ void k_spmm2(const __half* __restrict__ H, float* __restrict__ out) {
    int gw = (blockIdx.x * blockDim.x + threadIdx.x) >> 5;
    int lane = threadIdx.x & 31;
    int sub = lane >> 4;
    int sl  = lane & 15;
    int row = gw * 2 + sub;
    if (row >= NN) return;
    int n = __ldg(g_fill + NN + row);
    if (n > CAP) n = CAP;
    const int2*  bkt = g_bktA + (size_t)row * CAP;
    const int4*  b4  = (const int4*)bkt;
    const uint4* H4  = (const uint4*)H;
    uint64_t c0 = 0, c1 = 0, c2 = 0, c3 = 0;                 // packed f32x2 accs
    int j = 0;
    if (j + 3 < n) {
        int4 pA = __ldg(b4);
        int4 pB = __ldg(b4 + 1);
        for (; j + 3 < n; j += 4) {
            int kn = (j >> 1) + 2;
            int4 pA2 = __ldg(b4 + kn);       // prefetch next iteration's entries
            int4 pB2 = __ldg(b4 + kn + 1);
            uint4 q0 = __ldg(H4 + (size_t)pA.x * 16 + sl);
            uint4 q1 = __ldg(H4 + (size_t)pA.z * 16 + sl);
            uint4 q2 = __ldg(H4 + (size_t)pB.x * 16 + sl);
            uint4 q3 = __ldg(H4 + (size_t)pB.z * 16 + sl);
            fma_h16_p(c0, c1, c2, c3, bcast_f32x2(__int_as_float(pA.y)), q0);
            fma_h16_p(c0, c1, c2, c3, bcast_f32x2(__int_as_float(pA.w)), q1);
            fma_h16_p(c0, c1, c2, c3, bcast_f32x2(__int_as_float(pB.y)), q2);
            fma_h16_p(c0, c1, c2, c3, bcast_f32x2(__int_as_float(pB.w)), q3);
            pA = pA2; pB = pB2;
        }
    }
    for (; j < n; j++) {
        int2 cv = __ldg(bkt + j);
        uint4 q = __ldg(H4 + (size_t)cv.x * 16 + sl);
        fma_h16_p(c0, c1, c2, c3, bcast_f32x2(__int_as_float(cv.y)), q);
    }
    float4 a0, a1;
    unpack_f32x2(c0, a0.x, a0.y);
    unpack_f32x2(c1, a0.z, a0.w);
    unpack_f32x2(c2, a1.x, a1.y);
    unpack_f32x2(c3, a1.z, a1.w);
    a0.x = fmaxf(a0.x, 0.f); a0.y = fmaxf(a0.y, 0.f);
    a0.z = fmaxf(a0.z, 0.f); a0.w = fmaxf(a0.w, 0.f);
    a1.x = fmaxf(a1.x, 0.f); a1.y = fmaxf(a1.y, 0.f);
    a1.z = fmaxf(a1.z, 0.f); a1.w = fmaxf(a1.w, 0.f);
    float4* o4 = (float4*)out + (size_t)row * 32 + sl * 2;   // 8 floats = 2x float4
    o4[0] = a0;
    o4[1] = a1;
}

// ---------------------------------------------------------------------------
// Launch: 4 kernels; scatterA interleaved with spmm1 inside one launch
// ---------------------------------------------------------------------------
extern "C" void kernel_launch(void* const* d_in, const int* in_sizes, int n_in,
                              void* d_out, int out_size) {
    const int*   x_rows   = (const int*)  d_in[0];
    const int*   x_cols   = (const int*)  d_in[1];
    const float* x_vals   = (const float*)d_in[2];
    const int*   adj_rows = (const int*)  d_in[3];
    const int*   adj_cols = (const int*)  d_in[4];
    const float* adj_vals = (const float*)d_in[5];
    const float* W        = (const float*)d_in[6];
    float* out = (float*)d_out;

    __half* h_ptr;  cudaGetSymbolAddress((void**)&h_ptr, g_h);

    // 1. zero fill counters + convert W to fp16
    {
        int work = FILL_I4 + WCONV;
        k_prep<<<(work + 255) / 256, 256>>>(W);
    }

    // 2. scatter X into row buckets (dropout fused)
    k_scatter_x<<<SCAT_BLKS, 256>>>(x_rows, x_cols, x_vals);

    // 3. fused + interleaved: SpMM1 (2 of 3 blocks) || scatterA (1 of 3 blocks)
    k_spmm1_scatter_a<<<SPMM1_BLKS + SCAT_BLKS, 256>>>(adj_rows, adj_cols,
                                                       adj_vals, h_ptr);

    // 4. SpMM2 + ReLU: out = relu(A @ H)
    {
        long long threads = (long long)(NN / 2) * 32;
        int blocks = (int)((threads + 255) / 256);
        k_spmm2<<<blocks, 256>>>(h_ptr, out);
    }
}

// round 16
// speedup vs baseline: 1.1262x; 1.1262x over previous
#include <cuda_runtime.h>
#include <cuda_fp16.h>
#include <cstdint>
#include <cstring>

// Problem constants (fixed by the reference)
#define NN      100000
#define D_IN    256
#define D_OUT   128
#define NNZ_X   3200000
#define NNZ_A   3200000
#define INV_KEEP 1.1111112f   // float32(1/0.9), matching JAX

#define CAP     96            // bucket capacity per row; P(Poisson(32) > 96) ~ 1e-20

#define SCAT_BLKS   (NNZ_X / 4 / 256)      // 3125 blocks, 4 nnz/thread
#define SPMM1_BLKS  (NN / 16)              // 6250 blocks, 16 rows per block (8 warps x 2)

// ---------------------------------------------------------------------------
// Static scratch (no allocations allowed). +8 entry tail pad: the pipelined
// gather loops prefetch up to 2 entries past a row's CAP region.
// ---------------------------------------------------------------------------
__device__ __half g_h[(size_t)NN * D_OUT];          // 25.6 MB  H = X@W (fp16)
__device__ __half g_w16[D_IN * D_OUT];              // 64 KB    W in fp16
__device__ int    g_fill[2 * NN];                   // fillX | fillA
__device__ int2   g_bktX[(size_t)NN * CAP + 8];     // 76.8 MB (col, val-bits)
__device__ int2   g_bktA[(size_t)NN * CAP + 8];     // 76.8 MB

// bit-cast helpers
__device__ __forceinline__ uint32_t h2_to_u32(half2 h) {
    uint32_t u; memcpy(&u, &h, 4); return u;
}
__device__ __forceinline__ half2 u32_to_h2(uint32_t u) {
    half2 h; memcpy(&h, &u, 4); return h;
}

// ---------------------------------------------------------------------------
// threefry2x32, key = seed(42), partitionable mode: in = (0, i), out = o0^o1
// ---------------------------------------------------------------------------
__device__ __forceinline__ uint32_t rotl32(uint32_t v, int d) {
    return (v << d) | (v >> (32 - d));
}

__device__ __forceinline__ uint32_t threefry_bits_k42(uint32_t idx) {
    const uint32_t ks1 = 42u;
    const uint32_t ks2 = 42u ^ 0x1BD11BDAu;
    uint32_t x0 = 0u;
    uint32_t x1 = idx + ks1;
#define TF_ROUND(r) { x0 += x1; x1 = rotl32(x1, r); x1 ^= x0; }
    TF_ROUND(13) TF_ROUND(15) TF_ROUND(26) TF_ROUND(6)
    x0 += ks1; x1 += ks2 + 1u;
    TF_ROUND(17) TF_ROUND(29) TF_ROUND(16) TF_ROUND(24)
    x0 += ks2; x1 += 0u + 2u;
    TF_ROUND(13) TF_ROUND(15) TF_ROUND(26) TF_ROUND(6)
    x0 += 0u; x1 += ks1 + 3u;
    TF_ROUND(17) TF_ROUND(29) TF_ROUND(16) TF_ROUND(24)
    x0 += ks1; x1 += ks2 + 4u;
    TF_ROUND(13) TF_ROUND(15) TF_ROUND(26) TF_ROUND(6)
    x0 += ks2; x1 += 0u + 5u;
#undef TF_ROUND
    return x0 ^ x1;
}

__device__ __forceinline__ float bits_to_uniform(uint32_t bits) {
    return __uint_as_float((bits >> 9) | 0x3f800000u) - 1.0f;
}

// ---------------------------------------------------------------------------
// Prep: zero fill counters (2*NN ints = 50000 int4) + convert W to fp16
// ---------------------------------------------------------------------------
#define FILL_I4  (2 * NN / 4)                 // 50000
#define WCONV    (D_IN * D_OUT / 2)           // 16384 half2 outputs

__global__ void k_prep(const float* __restrict__ W) {
    int i = blockIdx.x * blockDim.x + threadIdx.x;
    if (i < FILL_I4) {
        ((int4*)g_fill)[i] = make_int4(0, 0, 0, 0);
    } else if (i < FILL_I4 + WCONV) {
        int j = i - FILL_I4;                   // half2 index
        float2 f = ((const float2*)W)[j];
        ((half2*)g_w16)[j] = __floats2half2_rn(f.x, f.y);
    }
}

// ---------------------------------------------------------------------------
// Scatter X into row buckets, 4 nnz per thread, dropout fused
// ---------------------------------------------------------------------------
__global__ void k_scatter_x(const int* __restrict__ x_rows,
                            const int* __restrict__ x_cols,
                            const float* __restrict__ x_vals) {
    int i = (blockIdx.x * blockDim.x + threadIdx.x) * 4;
    if (i >= NNZ_X) return;
    int4   r4 = __ldg((const int4*)(x_rows + i));
    int4   c4 = __ldg((const int4*)(x_cols + i));
    float4 v4 = __ldg((const float4*)(x_vals + i));
    #pragma unroll
    for (int k = 0; k < 4; k++) {
        int   r = (&r4.x)[k];
        int   c = (&c4.x)[k];
        float v = (&v4.x)[k];
        uint32_t bits = threefry_bits_k42((uint32_t)(i + k));
        float u = bits_to_uniform(bits);
        if (0.9f + u < 1.0f) continue;     // dropped, skip entirely
        int slot = atomicAdd(g_fill + r, 1);
        if (slot < CAP)
            g_bktX[(size_t)r * CAP + slot] =
                make_int2(c, __float_as_int(v * INV_KEEP));
    }
}

// ---------------------------------------------------------------------------
// fma of 8 halves (uint4) scaled by v into 8-float accumulator
// ---------------------------------------------------------------------------
__device__ __forceinline__ void fma_h16(float4& a0, float4& a1, float v, uint4 q) {
    float2 f0 = __half22float2(u32_to_h2(q.x));
    float2 f1 = __half22float2(u32_to_h2(q.y));
    float2 f2 = __half22float2(u32_to_h2(q.z));
    float2 f3 = __half22float2(u32_to_h2(q.w));
    a0.x = fmaf(v, f0.x, a0.x); a0.y = fmaf(v, f0.y, a0.y);
    a0.z = fmaf(v, f1.x, a0.z); a0.w = fmaf(v, f1.y, a0.w);
    a1.x = fmaf(v, f2.x, a1.x); a1.y = fmaf(v, f2.y, a1.y);
    a1.z = fmaf(v, f3.x, a1.z); a1.w = fmaf(v, f3.y, a1.w);
}

// ---------------------------------------------------------------------------
// Fused launch with INTERLEAVED roles: of every 3 consecutive blocks, 2 run
// SpMM1 and 1 runs scatterA, so both kinds coexist in every scheduling wave
// (a contiguous range split serializes across waves — measured in R12).
// ---------------------------------------------------------------------------
__global__ void k_spmm1_scatter_a(const int* __restrict__ a_rows,
                                  const int* __restrict__ a_cols,
                                  const float* __restrict__ a_vals,
                                  __half* __restrict__ H) {
    int b = blockIdx.x;
    int grp = b / 3;
    int rem = b - grp * 3;
    if (rem != 2) {
        // SpMM1 block index: 2 per group
        int sb = grp * 2 + rem;                  // < SPMM1_BLKS
        int lane = threadIdx.x & 31;
        int sub = lane >> 4;              // 0/1: which row of the pair
        int sl  = lane & 15;              // lane-within-row, owns cols [sl*8, sl*8+8)
        int row = sb * 16 + (threadIdx.x >> 5) * 2 + sub;
        int n = __ldg(g_fill + row);
        if (n > CAP) n = CAP;
        const int2*  bkt = g_bktX + (size_t)row * CAP;
        const int4*  b4  = (const int4*)bkt;                 // pair of entries
        const uint4* W4  = (const uint4*)g_w16;              // 8 halves per uint4
        float4 a0 = make_float4(0.f, 0.f, 0.f, 0.f);
        float4 a1 = make_float4(0.f, 0.f, 0.f, 0.f);
        int j = 0;
        if (j + 3 < n) {
            int4 pA = __ldg(b4);
            int4 pB = __ldg(b4 + 1);
            for (; j + 3 < n; j += 4) {
                int kn = (j >> 1) + 2;
                int4 pA2 = __ldg(b4 + kn);   // may overread into pad: unused then
                int4 pB2 = __ldg(b4 + kn + 1);
                uint4 q0 = __ldg(W4 + (size_t)pA.x * 16 + sl);
                uint4 q1 = __ldg(W4 + (size_t)pA.z * 16 + sl);
                uint4 q2 = __ldg(W4 + (size_t)pB.x * 16 + sl);
                uint4 q3 = __ldg(W4 + (size_t)pB.z * 16 + sl);
                fma_h16(a0, a1, __int_as_float(pA.y), q0);
                fma_h16(a0, a1, __int_as_float(pA.w), q1);
                fma_h16(a0, a1, __int_as_float(pB.y), q2);
                fma_h16(a0, a1, __int_as_float(pB.w), q3);
                pA = pA2; pB = pB2;
            }
        }
        for (; j < n; j++) {
            int2 cv = __ldg(bkt + j);
            uint4 q = __ldg(W4 + (size_t)cv.x * 16 + sl);
            fma_h16(a0, a1, __int_as_float(cv.y), q);
        }
        uint4 packed;
        packed.x = h2_to_u32(__floats2half2_rn(a0.x, a0.y));
        packed.y = h2_to_u32(__floats2half2_rn(a0.z, a0.w));
        packed.z = h2_to_u32(__floats2half2_rn(a1.x, a1.y));
        packed.w = h2_to_u32(__floats2half2_rn(a1.z, a1.w));
        ((uint4*)H)[(size_t)row * 16 + sl] = packed;
    } else {
        // scatterA block index: 1 per group
        int i = (grp * 256 + threadIdx.x) * 4;
        if (i >= NNZ_A) return;
        int4   r4 = __ldg((const int4*)(a_rows + i));
        int4   c4 = __ldg((const int4*)(a_cols + i));
        float4 v4 = __ldg((const float4*)(a_vals + i));
        #pragma unroll
        for (int k = 0; k < 4; k++) {
            int   r = (&r4.x)[k];
            int   c = (&c4.x)[k];
            float v = (&v4.x)[k];
            int slot = atomicAdd(g_fill + NN + r, 1);
            if (slot < CAP)
                g_bktA[(size_t)r * CAP + slot] = make_int2(c, __float_as_int(v));
        }
    }
}

// ---------------------------------------------------------------------------
// SpMM2 + ReLU: out(fp32) = relu(A @ H).  2 rows/warp, pipelined unroll 4.
// __launch_bounds__(256, 6): cap regs at 42 -> 6 blocks/SM (48 warps vs 40).
// ---------------------------------------------------------------------------
__global__ void __launch_bounds__(256, 6)
k_spmm2(const __half* __restrict__ H, float* __restrict__ out) {
    int gw = (blockIdx.x * blockDim.x + threadIdx.x) >> 5;
    int lane = threadIdx.x & 31;
    int sub = lane >> 4;
    int sl  = lane & 15;
    int row = gw * 2 + sub;
    if (row >= NN) return;
    int n = __ldg(g_fill + NN + row);
    if (n > CAP) n = CAP;
    const int2*  bkt = g_bktA + (size_t)row * CAP;
    const int4*  b4  = (const int4*)bkt;
    const uint4* H4  = (const uint4*)H;
    float4 a0 = make_float4(0.f, 0.f, 0.f, 0.f);
    float4 a1 = make_float4(0.f, 0.f, 0.f, 0.f);
    int j = 0;
    if (j + 3 < n) {
        int4 pA = __ldg(b4);
        int4 pB = __ldg(b4 + 1);
        for (; j + 3 < n; j += 4) {
            int kn = (j >> 1) + 2;
            int4 pA2 = __ldg(b4 + kn);       // prefetch next iteration's entries
            int4 pB2 = __ldg(b4 + kn + 1);
            uint4 q0 = __ldg(H4 + (size_t)pA.x * 16 + sl);
            uint4 q1 = __ldg(H4 + (size_t)pA.z * 16 + sl);
            uint4 q2 = __ldg(H4 + (size_t)pB.x * 16 + sl);
            uint4 q3 = __ldg(H4 + (size_t)pB.z * 16 + sl);
            fma_h16(a0, a1, __int_as_float(pA.y), q0);
            fma_h16(a0, a1, __int_as_float(pA.w), q1);
            fma_h16(a0, a1, __int_as_float(pB.y), q2);
            fma_h16(a0, a1, __int_as_float(pB.w), q3);
            pA = pA2; pB = pB2;
        }
    }
    for (; j < n; j++) {
        int2 cv = __ldg(bkt + j);
        uint4 q = __ldg(H4 + (size_t)cv.x * 16 + sl);
        fma_h16(a0, a1, __int_as_float(cv.y), q);
    }
    a0.x = fmaxf(a0.x, 0.f); a0.y = fmaxf(a0.y, 0.f);
    a0.z = fmaxf(a0.z, 0.f); a0.w = fmaxf(a0.w, 0.f);
    a1.x = fmaxf(a1.x, 0.f); a1.y = fmaxf(a1.y, 0.f);
    a1.z = fmaxf(a1.z, 0.f); a1.w = fmaxf(a1.w, 0.f);
    float4* o4 = (float4*)out + (size_t)row * 32 + sl * 2;   // 8 floats = 2x float4
    o4[0] = a0;
    o4[1] = a1;
}

// ---------------------------------------------------------------------------
// Launch: 4 kernels; scatterA interleaved with spmm1 inside one launch
// ---------------------------------------------------------------------------
extern "C" void kernel_launch(void* const* d_in, const int* in_sizes, int n_in,
                              void* d_out, int out_size) {
    const int*   x_rows   = (const int*)  d_in[0];
    const int*   x_cols   = (const int*)  d_in[1];
    const float* x_vals   = (const float*)d_in[2];
    const int*   adj_rows = (const int*)  d_in[3];
    const int*   adj_cols = (const int*)  d_in[4];
    const float* adj_vals = (const float*)d_in[5];
    const float* W        = (const float*)d_in[6];
    float* out = (float*)d_out;

    __half* h_ptr;  cudaGetSymbolAddress((void**)&h_ptr, g_h);

    // 1. zero fill counters + convert W to fp16
    {
        int work = FILL_I4 + WCONV;
        k_prep<<<(work + 255) / 256, 256>>>(W);
    }

    // 2. scatter X into row buckets (dropout fused)
    k_scatter_x<<<SCAT_BLKS, 256>>>(x_rows, x_cols, x_vals);

    // 3. fused + interleaved: SpMM1 (2 of 3 blocks) || scatterA (1 of 3 blocks)
    k_spmm1_scatter_a<<<SPMM1_BLKS + SCAT_BLKS, 256>>>(adj_rows, adj_cols,
                                                       adj_vals, h_ptr);

    // 4. SpMM2 + ReLU: out = relu(A @ H)
    {
        long long threads = (long long)(NN / 2) * 32;
        int blocks = (int)((threads + 255) / 256);
        k_spmm2<<<blocks, 256>>>(h_ptr, out);
    }
}